// round 17
// baseline (speedup 1.0000x reference)
#include <cuda_runtime.h>
#include <math.h>

#define NTOK 1024
#define DIMV 512
#define HIDV 2048
#define NEXP 64
#define MAXTILE 160

// ---------------- scratch (device globals; no allocation allowed) ----------
__device__ float g_h[NTOK * HIDV];            // hidden after GELU (8 MB)
__device__ float g_part[2 * NTOK * HIDV];     // K-split partials (16 MB shared)
__device__ float g_glog[8 * NTOK * NEXP];     // gating logit partials (2 MB)
__device__ int   g_idx[2][NTOK];
__device__ float g_gate[2][NTOK];
__device__ int   g_list[2][NTOK];
__device__ int   g_ntile[2];
__device__ int2  g_tiles[2][MAXTILE];         // x = e | (cnt<<16), y = base in g_list

// ---------------- packed f32x2 FMA (Blackwell) ------------------------------
__device__ __forceinline__ float2 ffma2(float2 a, float2 b, float2 c) {
    float2 d;
    asm("fma.rn.f32x2 %0, %1, %2, %3;"
        : "=l"(*reinterpret_cast<unsigned long long*>(&d))
        : "l"(*reinterpret_cast<const unsigned long long*>(&a)),
          "l"(*reinterpret_cast<const unsigned long long*>(&b)),
          "l"(*reinterpret_cast<const unsigned long long*>(&c)));
    return d;
}

__device__ __forceinline__ float4 ldcs4(const float* p) {
    float4 v;
    asm("ld.global.cs.v4.f32 {%0, %1, %2, %3}, [%4];"
        : "=f"(v.x), "=f"(v.y), "=f"(v.z), "=f"(v.w) : "l"(p));
    return v;
}

__device__ __forceinline__ float gelu_f(float v) {
    return 0.5f * v * (1.0f + erff(v * 0.70710678118654752440f));
}

// ---------------- gating logits: tiled GEMM [32 tok x 64 exp] per CTA --------
template<int DIN, int KLEN>
__global__ void glogit_kernel(const float* __restrict__ X,
                              const float* __restrict__ EMB,
                              float* __restrict__ GLOG) {
    const int t0 = blockIdx.x * 32;
    const int k0 = blockIdx.y * KLEN;
    const int eq = threadIdx.x & 15;
    const int tq = threadIdx.x >> 4;     // 0..7

    __shared__ float s_xT[64][36];       // [kk][token]
    __shared__ float s_e[64][66];        // [expert][kk]

    float2 acc[4][2];
    #pragma unroll
    for (int j = 0; j < 4; j++) {
        acc[j][0] = make_float2(0.f, 0.f);
        acc[j][1] = make_float2(0.f, 0.f);
    }

    for (int kc = 0; kc < KLEN; kc += 64) {
        __syncthreads();
        #pragma unroll
        for (int i = threadIdx.x; i < 512; i += 128) {
            int t = i >> 4, k4 = i & 15;
            float4 v = *(const float4*)(X + (size_t)(t0 + t) * DIN + k0 + kc + k4 * 4);
            s_xT[k4 * 4 + 0][t] = v.x;
            s_xT[k4 * 4 + 1][t] = v.y;
            s_xT[k4 * 4 + 2][t] = v.z;
            s_xT[k4 * 4 + 3][t] = v.w;
        }
        #pragma unroll
        for (int i = threadIdx.x; i < 1024; i += 128) {
            int e = i >> 4, k4 = i & 15;
            float4 v = *(const float4*)(EMB + (size_t)e * DIN + k0 + kc + k4 * 4);
            s_e[e][k4 * 4 + 0] = v.x;
            s_e[e][k4 * 4 + 1] = v.y;
            s_e[e][k4 * 4 + 2] = v.z;
            s_e[e][k4 * 4 + 3] = v.w;
        }
        __syncthreads();

        #pragma unroll 8
        for (int kk = 0; kk < 64; kk += 2) {
            float2 e0 = *(const float2*)&s_e[eq][kk];
            float2 e1 = *(const float2*)&s_e[eq + 16][kk];
            float2 e2 = *(const float2*)&s_e[eq + 32][kk];
            float2 e3 = *(const float2*)&s_e[eq + 48][kk];
            float4 x0 = *(const float4*)&s_xT[kk][tq * 4];
            float4 x1 = *(const float4*)&s_xT[kk + 1][tq * 4];

            float2 p0a = make_float2(e0.x, e1.x);
            float2 p1a = make_float2(e2.x, e3.x);
            float2 p0b = make_float2(e0.y, e1.y);
            float2 p1b = make_float2(e2.y, e3.y);

            acc[0][0] = ffma2(make_float2(x0.x, x0.x), p0a, acc[0][0]);
            acc[0][1] = ffma2(make_float2(x0.x, x0.x), p1a, acc[0][1]);
            acc[1][0] = ffma2(make_float2(x0.y, x0.y), p0a, acc[1][0]);
            acc[1][1] = ffma2(make_float2(x0.y, x0.y), p1a, acc[1][1]);
            acc[2][0] = ffma2(make_float2(x0.z, x0.z), p0a, acc[2][0]);
            acc[2][1] = ffma2(make_float2(x0.z, x0.z), p1a, acc[2][1]);
            acc[3][0] = ffma2(make_float2(x0.w, x0.w), p0a, acc[3][0]);
            acc[3][1] = ffma2(make_float2(x0.w, x0.w), p1a, acc[3][1]);

            acc[0][0] = ffma2(make_float2(x1.x, x1.x), p0b, acc[0][0]);
            acc[0][1] = ffma2(make_float2(x1.x, x1.x), p1b, acc[0][1]);
            acc[1][0] = ffma2(make_float2(x1.y, x1.y), p0b, acc[1][0]);
            acc[1][1] = ffma2(make_float2(x1.y, x1.y), p1b, acc[1][1]);
            acc[2][0] = ffma2(make_float2(x1.z, x1.z), p0b, acc[2][0]);
            acc[2][1] = ffma2(make_float2(x1.z, x1.z), p1b, acc[2][1]);
            acc[3][0] = ffma2(make_float2(x1.w, x1.w), p0b, acc[3][0]);
            acc[3][1] = ffma2(make_float2(x1.w, x1.w), p1b, acc[3][1]);
        }
    }

    #pragma unroll
    for (int j = 0; j < 4; j++) {
        float* gp = GLOG + ((size_t)blockIdx.y * NTOK + t0 + tq * 4 + j) * NEXP;
        gp[eq]      = acc[j][0].x;
        gp[eq + 16] = acc[j][0].y;
        gp[eq + 32] = acc[j][1].x;
        gp[eq + 48] = acc[j][1].y;
    }
}

// ---------------- gating finalize: softmax max-prob + argmax -----------------
template<int NSPLIT>
__global__ void gfinal_kernel(const float* __restrict__ GLOG,
                              float scale, int layer) {
    const int t = blockIdx.x;
    const int l = threadIdx.x;
    float v0 = 0.f, v1 = 0.f;
    #pragma unroll
    for (int z = 0; z < NSPLIT; z++) {
        const float* gp = GLOG + ((size_t)z * NTOK + t) * NEXP;
        v0 += gp[l];
        v1 += gp[l + 32];
    }
    v0 *= scale; v1 *= scale;

    float m; int mi;
    if (v0 >= v1) { m = v0; mi = l; } else { m = v1; mi = l + 32; }
    #pragma unroll
    for (int off = 16; off; off >>= 1) {
        float om = __shfl_xor_sync(0xFFFFFFFFu, m, off);
        int omi = __shfl_xor_sync(0xFFFFFFFFu, mi, off);
        if (om > m || (om == m && omi < mi)) { m = om; mi = omi; }
    }
    float s = expf(v0 - m) + expf(v1 - m);
    #pragma unroll
    for (int off = 16; off; off >>= 1)
        s += __shfl_xor_sync(0xFFFFFFFFu, s, off);

    if (l == 0) {
        g_idx[layer][t]  = mi;
        g_gate[layer][t] = 1.0f / s;   // max softmax prob
    }
}

// ---------------- group: histogram + prefix + scatter + tile list ------------
__global__ void group_kernel(int layer) {
    __shared__ int s_cnt[NEXP], s_cur[NEXP];
    const int t = threadIdx.x;
    if (t < NEXP) s_cnt[t] = 0;
    __syncthreads();
    for (int i = t; i < NTOK; i += blockDim.x)
        atomicAdd(&s_cnt[g_idx[layer][i]], 1);
    __syncthreads();
    if (t == 0) {
        int a = 0, nt = 0;
        for (int e = 0; e < NEXP; e++) {
            s_cur[e] = a;
            const int c = s_cnt[e];
            for (int t0 = 0; t0 < c; t0 += 16) {
                int cnt = (c - t0 < 16) ? (c - t0) : 16;
                g_tiles[layer][nt++] = make_int2(e | (cnt << 16), a + t0);
            }
            a += c;
        }
        g_ntile[layer] = nt;
    }
    __syncthreads();
    for (int i = t; i < NTOK; i += blockDim.x) {
        int e = g_idx[layer][i];
        int p = atomicAdd(&s_cur[e], 1);
        g_list[layer][p] = i;
    }
}

// ---------------- FMA micro-block: 4 k-rows x 16 tokens x 4 cols --------------
// One LDS.128 per token feeds 8 FFMA2 (4 rows x 2 col-pairs).
template<int KLEN>
__device__ __forceinline__ void fma_block4(float2 (&acc)[16][2],
                                           const float (&s_x)[16][KLEN],
                                           int kb, const float4 (&wb)[4]) {
    #pragma unroll
    for (int j = 0; j < 16; j++) {
        float4 xa = *(const float4*)&s_x[j][kb];      // broadcast LDS.128
        acc[j][0] = ffma2(make_float2(xa.x, xa.x), make_float2(wb[0].x, wb[0].y), acc[j][0]);
        acc[j][1] = ffma2(make_float2(xa.x, xa.x), make_float2(wb[0].z, wb[0].w), acc[j][1]);
        acc[j][0] = ffma2(make_float2(xa.y, xa.y), make_float2(wb[1].x, wb[1].y), acc[j][0]);
        acc[j][1] = ffma2(make_float2(xa.y, xa.y), make_float2(wb[1].z, wb[1].w), acc[j][1]);
        acc[j][0] = ffma2(make_float2(xa.z, xa.z), make_float2(wb[2].x, wb[2].y), acc[j][0]);
        acc[j][1] = ffma2(make_float2(xa.z, xa.z), make_float2(wb[2].z, wb[2].w), acc[j][1]);
        acc[j][0] = ffma2(make_float2(xa.w, xa.w), make_float2(wb[3].x, wb[3].y), acc[j][0]);
        acc[j][1] = ffma2(make_float2(xa.w, xa.w), make_float2(wb[3].z, wb[3].w), acc[j][1]);
    }
}

// ---------------- grouped expert FC: one 16-token tile per CTA ---------------
// grid = (DOUT/512, 128 slots, DIN/KLEN); 128 threads.
// Warp wg owns cols [blk*512 + wg*128, +128); lane owns 4 cols (LDG.128 W).
// Double-buffered 4-row W batches. Raw partial sums out.
template<int DIN, int DOUT, int KLEN>
__global__ void __launch_bounds__(128, 4)
fc_kernel(const float* __restrict__ X,
          const float* __restrict__ W,
          int layer,
          float* __restrict__ OUT) {
    const int slot = blockIdx.y;
    if (slot >= g_ntile[layer]) return;
    const int2 tile = g_tiles[layer][slot];
    const int e = tile.x & 0xFFFF;
    const int cnt = tile.x >> 16;
    const int tbase = tile.y;

    const int lane = threadIdx.x & 31;
    const int wg = threadIdx.x >> 5;
    const int colBase = blockIdx.x * 512 + wg * 128 + lane * 4;
    const int k0 = blockIdx.z * KLEN;

    __shared__ float s_x[16][KLEN];
    __shared__ int s_row[16];

    const float* Wb = W + (size_t)e * DIN * DOUT + (size_t)k0 * DOUT + colBase;

    // preload both W batches early (hide under X staging)
    float4 wb0[4], wb1[4];
    #pragma unroll
    for (int u = 0; u < 4; u++) wb0[u] = ldcs4(Wb + (size_t)u * DOUT);
    #pragma unroll
    for (int u = 0; u < 4; u++) wb1[u] = ldcs4(Wb + (size_t)(4 + u) * DOUT);

    if (threadIdx.x < 16)
        s_row[threadIdx.x] = (threadIdx.x < cnt)
                             ? g_list[layer][tbase + threadIdx.x] : -1;
    __syncthreads();

    // stage 16 x KLEN chunk of X (float4, coalesced)
    constexpr int K4 = KLEN / 4;
    #pragma unroll
    for (int i = threadIdx.x; i < 16 * K4; i += 128) {
        int t = i / K4, k4 = i % K4;
        int r = s_row[t];
        float4 v = (r >= 0)
            ? *(const float4*)(X + (size_t)r * DIN + k0 + k4 * 4)
            : make_float4(0.f, 0.f, 0.f, 0.f);
        *(float4*)&s_x[t][k4 * 4] = v;
    }
    __syncthreads();

    float2 acc[16][2];
    #pragma unroll
    for (int j = 0; j < 16; j++) {
        acc[j][0] = make_float2(0.f, 0.f);
        acc[j][1] = make_float2(0.f, 0.f);
    }

    #pragma unroll 1
    for (int kb = 0; kb < KLEN; kb += 8) {
        fma_block4<KLEN>(acc, s_x, kb, wb0);
        if (kb + 8 < KLEN) {
            const float* wn = Wb + (size_t)(kb + 8) * DOUT;
            #pragma unroll
            for (int u = 0; u < 4; u++) wb0[u] = ldcs4(wn + (size_t)u * DOUT);
        }
        fma_block4<KLEN>(acc, s_x, kb + 4, wb1);
        if (kb + 12 < KLEN) {
            const float* wn = Wb + (size_t)(kb + 12) * DOUT;
            #pragma unroll
            for (int u = 0; u < 4; u++) wb1[u] = ldcs4(wn + (size_t)u * DOUT);
        }
    }

    // write raw partial sums (per-split slab)
    #pragma unroll
    for (int j = 0; j < 16; j++) {
        int r = s_row[j];
        if (r < 0) continue;
        *(float4*)(OUT + ((size_t)blockIdx.z * NTOK + r) * DOUT + colBase) =
            make_float4(acc[j][0].x, acc[j][0].y, acc[j][1].x, acc[j][1].y);
    }
}

// ---------------- FC1 combine: bias + gate + gelu -> h -----------------------
__global__ void epi1_kernel(const float* __restrict__ B1v,
                            float* __restrict__ H) {
    const int t = blockIdx.x;
    const int c = threadIdx.x * 4;
    const int e = g_idx[0][t];
    const float g = g_gate[0][t];
    float4 s = *(const float4*)(B1v + (size_t)e * HIDV + c);
    #pragma unroll
    for (int z = 0; z < 2; z++) {
        float4 p = *(const float4*)&g_part[((size_t)z * NTOK + t) * HIDV + c];
        s.x += p.x; s.y += p.y; s.z += p.z; s.w += p.w;
    }
    *(float4*)(H + (size_t)t * HIDV + c) =
        make_float4(gelu_f(s.x * g), gelu_f(s.y * g),
                    gelu_f(s.z * g), gelu_f(s.w * g));
}

// ---------------- FC2 combine: bias + gate -> out ----------------------------
__global__ void epi2_kernel(const float* __restrict__ B2v,
                            float* __restrict__ OUT) {
    const int t = blockIdx.x;
    const int c = threadIdx.x * 4;
    const int e = g_idx[1][t];
    const float g = g_gate[1][t];
    float4 s = *(const float4*)(B2v + (size_t)e * DIMV + c);
    #pragma unroll
    for (int z = 0; z < 8; z++) {
        float4 p = *(const float4*)&g_part[((size_t)z * NTOK + t) * DIMV + c];
        s.x += p.x; s.y += p.y; s.z += p.z; s.w += p.w;
    }
    *(float4*)(OUT + (size_t)t * DIMV + c) =
        make_float4(s.x * g, s.y * g, s.z * g, s.w * g);
}

// ---------------- launch ------------------------------------------------------
extern "C" void kernel_launch(void* const* d_in, const int* in_sizes, int n_in,
                              void* d_out, int out_size) {
    const float* x    = (const float*)d_in[0];
    const float* emb1 = (const float*)d_in[1];
    const float* W1   = (const float*)d_in[2];
    const float* b1   = (const float*)d_in[3];
    const float* emb2 = (const float*)d_in[4];
    const float* W2   = (const float*)d_in[5];
    const float* b2   = (const float*)d_in[6];
    float* out = (float*)d_out;

    void* hp = nullptr;
    cudaGetSymbolAddress(&hp, g_h);
    float* h = (float*)hp;
    void* pp = nullptr;
    cudaGetSymbolAddress(&pp, g_part);
    float* part = (float*)pp;
    void* gp = nullptr;
    cudaGetSymbolAddress(&gp, g_glog);
    float* glog = (float*)gp;

    const float scale1 = 0.044194173824159216f;   // 1/sqrt(512)
    const float scale2 = 0.022097086912079612f;   // 1/sqrt(2048)

    // layer-1 gating: tiled logit GEMM (K split x2) + finalize
    glogit_kernel<DIMV, 256><<<dim3(NTOK / 32, 2), 128>>>(x, emb1, glog);
    gfinal_kernel<2><<<NTOK, 32>>>(glog, scale1, 0);
    group_kernel<<<1, 256>>>(0);
    // FC1: K=512 split x2 (KLEN=256), one tile per CTA, 128 tile slots
    fc_kernel<DIMV, HIDV, 256>
        <<<dim3(HIDV / 512, 128, 2), 128>>>(x, W1, 0, part);
    epi1_kernel<<<NTOK, 512>>>(b1, h);

    // layer-2 gating (K split x8)
    glogit_kernel<HIDV, 256><<<dim3(NTOK / 32, 8), 128>>>(h, emb2, glog);
    gfinal_kernel<8><<<NTOK, 32>>>(glog, scale2, 1);
    group_kernel<<<1, 256>>>(1);
    // FC2: K=2048 split x8 (KLEN=256), one tile per CTA
    fc_kernel<HIDV, DIMV, 256>
        <<<dim3(DIMV / 512, 128, 8), 128>>>(h, W2, 1, part);
    epi2_kernel<<<NTOK, 128>>>(b2, out);
}